// round 2
// baseline (speedup 1.0000x reference)
#include <cuda_runtime.h>
#include <cuda_bf16.h>

// SurvivalGeometryRegularizer:
//   mask[i][j] = (time[i] < time[j]) && (event[i] == 1)
//   hinge      = relu(1 + risk[i] - risk[j])
//   out        = sum(mask*hinge) / sum(mask)  (0 if count==0)
// z (d_in[0]) is UNUSED. Inputs: [1]=risk f32[B], [2]=time f32[B], [3]=event i32[B].
//
// Strategy: (1) deterministic single-block compaction of event rows ->
// (t_i, 1+r_i) arrays + NE, halving O(B^2) work; (2) issue-bound pairwise
// kernel, 4 i's/thread amortizing the smem j-tile load (~5.25 instr/pair);
// (3) shuffle-based finalize. No atomics anywhere -> bitwise deterministic.

#define BNUM  8192
#define TPB   256
#define IPT   4
#define ITILE (TPB * IPT)      // 1024 i per block
#define IB    (BNUM / ITILE)   // 8 (worst case NE = 8192)
#define JT    64
#define JB    (BNUM / JT)      // 128
#define NPART (IB * JB)        // 1024 partial slots

__device__ float g_ct[BNUM];   // compacted time of event rows
__device__ float g_ca[BNUM];   // compacted 1 + risk of event rows
__device__ int   g_ne;         // number of event rows
__device__ float g_ps[NPART];  // per-block partial sums
__device__ int   g_pc[NPART];  // per-block partial counts

// ---------------------------------------------------------------------------
// Deterministic compaction: single block, exact integer prefix scan.
// ---------------------------------------------------------------------------
__global__ __launch_bounds__(1024) void compact_kernel(
    const float* __restrict__ risk, const float* __restrict__ time_,
    const int* __restrict__ event)
{
    __shared__ int s_wsum[32];
    __shared__ int s_wincl[32];
    const int tid  = threadIdx.x;
    const int lane = tid & 31;
    const int wid  = tid >> 5;
    const int base = tid * 8;          // contiguous 8-element chunk per thread

    int ev[8];
    const int4* e4 = reinterpret_cast<const int4*>(event + base);
    const int4 ea = e4[0], eb = e4[1];
    ev[0]=ea.x; ev[1]=ea.y; ev[2]=ea.z; ev[3]=ea.w;
    ev[4]=eb.x; ev[5]=eb.y; ev[6]=eb.z; ev[7]=eb.w;

    int local = 0;
    #pragma unroll
    for (int k = 0; k < 8; k++) local += ev[k];

    // inclusive warp scan of per-thread counts
    int incl = local;
    #pragma unroll
    for (int off = 1; off < 32; off <<= 1) {
        int y = __shfl_up_sync(0xffffffffu, incl, off);
        if (lane >= off) incl += y;
    }
    if (lane == 31) s_wsum[wid] = incl;
    __syncthreads();

    if (wid == 0) {
        int vi = s_wsum[lane];
        #pragma unroll
        for (int off = 1; off < 32; off <<= 1) {
            int y = __shfl_up_sync(0xffffffffu, vi, off);
            if (lane >= off) vi += y;
        }
        s_wincl[lane] = vi;
        if (lane == 31) g_ne = vi;     // total event count
    }
    __syncthreads();

    int off = (wid ? s_wincl[wid - 1] : 0) + (incl - local);  // exclusive base
    #pragma unroll
    for (int k = 0; k < 8; k++) {
        if (ev[k]) {
            const int i = base + k;
            g_ct[off] = time_[i];
            g_ca[off] = 1.0f + risk[i];
            off++;
        }
    }
}

// ---------------------------------------------------------------------------
// Pairwise hinge: grid (IB, JB). Each thread owns IPT compacted i-rows,
// inner loop over a JT-wide (t_j, -r_j) smem tile.
// ---------------------------------------------------------------------------
__global__ __launch_bounds__(TPB) void pair_kernel(
    const float* __restrict__ risk, const float* __restrict__ time_)
{
    __shared__ float2 sj[JT];
    __shared__ float  s_rs[TPB / 32];
    __shared__ int    s_rc[TPB / 32];

    const int tid  = threadIdx.x;
    const int slot = blockIdx.y * IB + blockIdx.x;
    const int ne   = g_ne;
    const int ibase = blockIdx.x * ITILE;

    if (ibase >= ne) {               // whole block beyond compacted range
        if (tid == 0) { g_ps[slot] = 0.0f; g_pc[slot] = 0; }
        return;
    }

    const int j0 = blockIdx.y * JT;
    if (tid < JT) sj[tid] = make_float2(time_[j0 + tid], -risk[j0 + tid]);

    const float INF = __int_as_float(0x7f800000);
    float ti[IPT], ai[IPT], s[IPT];
    int   c[IPT];
    #pragma unroll
    for (int m = 0; m < IPT; m++) {
        const int i = ibase + m * TPB + tid;
        const bool v = i < ne;
        ti[m] = v ? g_ct[i] : INF;   // INF -> strict compare always false
        ai[m] = v ? g_ca[i] : 0.0f;
        s[m] = 0.0f; c[m] = 0;
    }
    __syncthreads();

    #pragma unroll 8
    for (int k = 0; k < JT; k++) {
        const float2 v = sj[k];      // broadcast LDS.64, amortized over IPT pairs
        #pragma unroll
        for (int m = 0; m < IPT; m++) {
            const float d = ai[m] + v.y;        // (1 + r_i) - r_j
            const float h = fmaxf(d, 0.0f);
            if (ti[m] < v.x) {                   // predicated FADD / IADD
                s[m] += h;
                c[m] += 1;
            }
        }
    }

    float ss = (s[0] + s[1]) + (s[2] + s[3]);
    int   cc = (c[0] + c[1]) + (c[2] + c[3]);

    #pragma unroll
    for (int off = 16; off > 0; off >>= 1) {
        ss += __shfl_down_sync(0xffffffffu, ss, off);
        cc += __shfl_down_sync(0xffffffffu, cc, off);
    }
    const int lane = tid & 31, wid = tid >> 5;
    if (lane == 0) { s_rs[wid] = ss; s_rc[wid] = cc; }
    __syncthreads();

    if (wid == 0) {
        float sv = (lane < TPB / 32) ? s_rs[lane] : 0.0f;
        int   cv = (lane < TPB / 32) ? s_rc[lane] : 0;
        #pragma unroll
        for (int off = 4; off > 0; off >>= 1) {
            sv += __shfl_down_sync(0xffffffffu, sv, off);
            cv += __shfl_down_sync(0xffffffffu, cv, off);
        }
        if (lane == 0) { g_ps[slot] = sv; g_pc[slot] = cv; }
    }
}

// ---------------------------------------------------------------------------
// Finalize: shuffle-based reduction of NPART fixed slots (1 __syncthreads).
// ---------------------------------------------------------------------------
__global__ __launch_bounds__(512) void finalize_kernel(float* __restrict__ out)
{
    __shared__ double    s_s[16];
    __shared__ long long s_c[16];
    const int tid = threadIdx.x, lane = tid & 31, wid = tid >> 5;

    double    s = (double)g_ps[tid] + (double)g_ps[tid + 512];
    long long c = (long long)g_pc[tid] + (long long)g_pc[tid + 512];

    #pragma unroll
    for (int off = 16; off > 0; off >>= 1) {
        s += __shfl_down_sync(0xffffffffu, s, off);
        c += __shfl_down_sync(0xffffffffu, c, off);
    }
    if (lane == 0) { s_s[wid] = s; s_c[wid] = c; }
    __syncthreads();

    if (wid == 0) {
        double    sv = (lane < 16) ? s_s[lane] : 0.0;
        long long cv = (lane < 16) ? s_c[lane] : 0;
        #pragma unroll
        for (int off = 8; off > 0; off >>= 1) {
            sv += __shfl_down_sync(0xffffffffu, sv, off);
            cv += __shfl_down_sync(0xffffffffu, cv, off);
        }
        if (lane == 0) out[0] = cv ? (float)(sv / (double)cv) : 0.0f;
    }
}

extern "C" void kernel_launch(void* const* d_in, const int* in_sizes, int n_in,
                              void* d_out, int out_size)
{
    // d_in[0] = z (unused)
    const float* risk  = (const float*)d_in[1];
    const float* time_ = (const float*)d_in[2];
    const int*   event = (const int*)d_in[3];

    compact_kernel<<<1, 1024>>>(risk, time_, event);
    dim3 grid(IB, JB);
    pair_kernel<<<grid, TPB>>>(risk, time_);
    finalize_kernel<<<1, 512>>>((float*)d_out);
}

// round 4
// speedup vs baseline: 1.0761x; 1.0761x over previous
#include <cuda_runtime.h>
#include <cuda_bf16.h>

// SurvivalGeometryRegularizer:
//   mask[i][j] = (time[i] < time[j]) && (event[i] == 1)
//   hinge      = relu(1 + risk[i] - risk[j])
//   out        = sum(mask*hinge) / sum(mask)   (0 if count==0)
// z (d_in[0]) is UNUSED. Inputs: [1]=risk f32[B], [2]=time f32[B], [3]=event i32[B].
//
// Single fused kernel:
//  - each block compacts its 256-row i-slice (event rows only) into smem via
//    an intra-block prefix scan  -> 2x work reduction at ~100-cycle cost
//  - each thread holds 4 j-columns in registers; inner loop over compacted
//    i-entries (broadcast LDS.64, ~5.25 warp-instr/pair)
//  - last-arriving block (threadfence + ticket) reduces the 256 fixed partial
//    slots in fixed order -> bitwise deterministic, no extra launches.
//    Ticket is reset to 0 by the last block => graph-replay safe.

#define BNUM  8192
#define TPB   256
#define IT    256                 // i-rows per block
#define IBLK  (BNUM / IT)         // 32
#define JPT   4                   // j-columns per thread
#define JTILE (TPB * JPT)         // 1024
#define JBLK  (BNUM / JTILE)      // 8
#define NPART (IBLK * JBLK)       // 256 blocks / partial slots

__device__ float        g_ps[NPART];
__device__ int          g_pc[NPART];
__device__ unsigned int g_ticket;   // zero-init at load; last block resets to 0

__global__ __launch_bounds__(TPB) void fused_pair_kernel(
    const float* __restrict__ risk,
    const float* __restrict__ time_,
    const int*   __restrict__ event,
    float*       __restrict__ out)
{
    __shared__ float2    s_i[IT];          // compacted (t_i, 1+r_i)
    __shared__ int       s_wsum[TPB / 32]; // per-warp scan totals
    __shared__ int       s_lne;            // compacted count in this block
    __shared__ float     s_rs[TPB / 32];
    __shared__ int       s_rc[TPB / 32];
    __shared__ int       s_islast;
    __shared__ double    f_s[TPB / 32];
    __shared__ long long f_c[TPB / 32];

    const int tid  = threadIdx.x;
    const int lane = tid & 31;
    const int wid  = tid >> 5;
    const int bid  = blockIdx.y * IBLK + blockIdx.x;

    // ---- load this block's i-slice (coalesced) --------------------------
    const int i  = blockIdx.x * IT + tid;
    const int ev = event[i];
    const float tiv = time_[i];
    const float aiv = 1.0f + risk[i];

    // ---- load this thread's 4 j-columns (coalesced) ---------------------
    const int j0 = blockIdx.y * JTILE;
    float tj[JPT], nrj[JPT];
    #pragma unroll
    for (int m = 0; m < JPT; m++) {
        const int j = j0 + m * TPB + tid;
        tj[m]  = time_[j];
        nrj[m] = -risk[j];
    }

    // ---- intra-block compaction of event rows into smem -----------------
    int incl = ev;                      // inclusive warp scan
    #pragma unroll
    for (int off = 1; off < 32; off <<= 1) {
        int y = __shfl_up_sync(0xffffffffu, incl, off);
        if (lane >= off) incl += y;
    }
    if (lane == 31) s_wsum[wid] = incl;
    __syncthreads();

    if (wid == 0) {
        int v = (lane < TPB / 32) ? s_wsum[lane] : 0;
        #pragma unroll
        for (int off = 1; off < TPB / 32; off <<= 1) {
            int y = __shfl_up_sync(0xffffffffu, v, off);
            if (lane >= off) v += y;
        }
        if (lane < TPB / 32) s_wsum[lane] = v;      // inclusive warp totals
        if (lane == TPB / 32 - 1) s_lne = v;        // block's event count
    }
    __syncthreads();

    {
        const int base = (wid ? s_wsum[wid - 1] : 0) + (incl - ev);
        if (ev) s_i[base] = make_float2(tiv, aiv);
    }
    __syncthreads();

    // ---- main pairwise loop ---------------------------------------------
    const int lne = s_lne;
    float s[JPT];
    int   c[JPT];
    #pragma unroll
    for (int m = 0; m < JPT; m++) { s[m] = 0.0f; c[m] = 0; }

    #pragma unroll 4
    for (int k = 0; k < lne; k++) {
        const float2 v = s_i[k];        // broadcast LDS.64
        #pragma unroll
        for (int m = 0; m < JPT; m++) {
            const float h = fmaxf(v.y + nrj[m], 0.0f); // (1+r_i) - r_j
            if (v.x < tj[m]) {                          // t_i < t_j (event-only i)
                s[m] += h;
                c[m] += 1;
            }
        }
    }

    float ss = (s[0] + s[1]) + (s[2] + s[3]);
    int   cc = (c[0] + c[1]) + (c[2] + c[3]);

    // ---- deterministic intra-block reduction -----------------------------
    #pragma unroll
    for (int off = 16; off > 0; off >>= 1) {
        ss += __shfl_down_sync(0xffffffffu, ss, off);
        cc += __shfl_down_sync(0xffffffffu, cc, off);
    }
    if (lane == 0) { s_rs[wid] = ss; s_rc[wid] = cc; }
    __syncthreads();

    if (tid == 0) {
        float sv = 0.0f;
        int   cv = 0;
        #pragma unroll
        for (int w = 0; w < TPB / 32; w++) { sv += s_rs[w]; cv += s_rc[w]; }
        g_ps[bid] = sv;
        g_pc[bid] = cv;
    }

    // ---- last-block fused finalize (threadfence + ticket) ----------------
    __threadfence();
    if (tid == 0) {
        const unsigned t = atomicAdd(&g_ticket, 1u);
        s_islast = (t == NPART - 1) ? 1 : 0;
    }
    __syncthreads();

    if (s_islast) {
        __threadfence();                // all partials now visible
        double    sv = (double)g_ps[tid];        // NPART == TPB == 256
        long long cv = (long long)g_pc[tid];
        #pragma unroll
        for (int off = 16; off > 0; off >>= 1) {
            sv += __shfl_down_sync(0xffffffffu, sv, off);
            cv += __shfl_down_sync(0xffffffffu, cv, off);
        }
        if (lane == 0) { f_s[wid] = sv; f_c[wid] = cv; }
        __syncthreads();
        if (tid == 0) {
            double    ts = 0.0;
            long long tc = 0;
            #pragma unroll
            for (int w = 0; w < TPB / 32; w++) { ts += f_s[w]; tc += f_c[w]; }
            out[0] = tc ? (float)(ts / (double)tc) : 0.0f;
            g_ticket = 0;               // reset for next graph replay
        }
    }
}

extern "C" void kernel_launch(void* const* d_in, const int* in_sizes, int n_in,
                              void* d_out, int out_size)
{
    // d_in[0] = z (unused)
    const float* risk  = (const float*)d_in[1];
    const float* time_ = (const float*)d_in[2];
    const int*   event = (const int*)d_in[3];

    dim3 grid(IBLK, JBLK);
    fused_pair_kernel<<<grid, TPB>>>(risk, time_, event, (float*)d_out);
}

// round 5
// speedup vs baseline: 1.4859x; 1.3809x over previous
#include <cuda_runtime.h>
#include <cuda_bf16.h>

// SurvivalGeometryRegularizer:
//   mask[i][j] = (time[i] < time[j]) && (event[i] == 1)
//   hinge      = relu(1 + risk[i] - risk[j])
//   out        = sum(mask*hinge) / sum(mask)   (0 if count==0)
// z (d_in[0]) is UNUSED. Inputs: [1]=risk f32[B], [2]=time f32[B], [3]=event i32[B].
//
// R5: exactly one wave of 592 blocks (4/SM on 148 SMs) -> no wave-quantization
// tail (R4 lost 2x to 256 blocks / 148 SMs = 1.73 waves).
//   - 74 i-splits x 8 j-splits; i-range per block computed as bi*B/74 (110-111
//     rows, <=1% imbalance)
//   - per-block smem compaction of event rows (2x work cut)
//   - 4 j-columns per thread in registers; inner loop = broadcast LDS.64 +
//     4x predicated hinge (~5.25 warp-instr/pair)
//   - last-arriving block (threadfence + ticket) reduces 592 fixed slots in
//     fixed order -> bitwise deterministic; ticket reset => graph-replay safe.

#define BNUM   8192
#define TPB    256
#define ISPLIT 74
#define JSPLIT 8
#define JPT    4
#define JTILE  (TPB * JPT)        // 1024
#define NPART  (ISPLIT * JSPLIT)  // 592 blocks / partial slots
#define MAXROW 128                // max rows per i-split (<= 111 actual)

__device__ float        g_ps[NPART];
__device__ int          g_pc[NPART];
__device__ unsigned int g_ticket;   // zero-init at load; last block resets to 0

__global__ __launch_bounds__(TPB) void fused_pair_kernel(
    const float* __restrict__ risk,
    const float* __restrict__ time_,
    const int*   __restrict__ event,
    float*       __restrict__ out)
{
    __shared__ float2    s_i[MAXROW];      // compacted (t_i, 1+r_i)
    __shared__ int       s_wsum[TPB / 32];
    __shared__ int       s_lne;
    __shared__ float     s_rs[TPB / 32];
    __shared__ int       s_rc[TPB / 32];
    __shared__ int       s_islast;
    __shared__ double    f_s[TPB / 32];
    __shared__ long long f_c[TPB / 32];

    const int tid  = threadIdx.x;
    const int lane = tid & 31;
    const int wid  = tid >> 5;
    const int bid  = blockIdx.y * ISPLIT + blockIdx.x;

    // ---- this block's i-range (balanced split of 8192 over 74) ----------
    const int ilo  = (int)(((long long)blockIdx.x * BNUM) / ISPLIT);
    const int ihi  = (int)(((long long)(blockIdx.x + 1) * BNUM) / ISPLIT);
    const int rows = ihi - ilo;             // 110 or 111

    const int   inr = tid < rows;
    const int   i   = ilo + tid;
    const int   ev  = inr ? event[i] : 0;
    const float tiv = inr ? time_[i] : 0.0f;
    const float aiv = inr ? (1.0f + risk[i]) : 0.0f;

    // ---- this thread's 4 j-columns (coalesced) ---------------------------
    const int j0 = blockIdx.y * JTILE;
    float tj[JPT], nrj[JPT];
    #pragma unroll
    for (int m = 0; m < JPT; m++) {
        const int j = j0 + m * TPB + tid;
        tj[m]  = time_[j];
        nrj[m] = -risk[j];
    }

    // ---- intra-block compaction of event rows into smem ------------------
    int incl = ev;
    #pragma unroll
    for (int off = 1; off < 32; off <<= 1) {
        int y = __shfl_up_sync(0xffffffffu, incl, off);
        if (lane >= off) incl += y;
    }
    if (lane == 31) s_wsum[wid] = incl;
    __syncthreads();

    if (wid == 0) {
        int v = (lane < TPB / 32) ? s_wsum[lane] : 0;
        #pragma unroll
        for (int off = 1; off < TPB / 32; off <<= 1) {
            int y = __shfl_up_sync(0xffffffffu, v, off);
            if (lane >= off) v += y;
        }
        if (lane < TPB / 32) s_wsum[lane] = v;
        if (lane == TPB / 32 - 1) s_lne = v;
    }
    __syncthreads();

    {
        const int base = (wid ? s_wsum[wid - 1] : 0) + (incl - ev);
        if (ev) s_i[base] = make_float2(tiv, aiv);
    }
    __syncthreads();

    // ---- main pairwise loop ----------------------------------------------
    const int lne = s_lne;                 // ~55 event rows
    float s[JPT];
    int   c[JPT];
    #pragma unroll
    for (int m = 0; m < JPT; m++) { s[m] = 0.0f; c[m] = 0; }

    #pragma unroll 4
    for (int k = 0; k < lne; k++) {
        const float2 v = s_i[k];           // broadcast LDS.64
        #pragma unroll
        for (int m = 0; m < JPT; m++) {
            const float h = fmaxf(v.y + nrj[m], 0.0f); // (1+r_i) - r_j
            if (v.x < tj[m]) {                          // t_i < t_j
                s[m] += h;
                c[m] += 1;
            }
        }
    }

    float ss = (s[0] + s[1]) + (s[2] + s[3]);
    int   cc = (c[0] + c[1]) + (c[2] + c[3]);

    // ---- deterministic intra-block reduction -----------------------------
    #pragma unroll
    for (int off = 16; off > 0; off >>= 1) {
        ss += __shfl_down_sync(0xffffffffu, ss, off);
        cc += __shfl_down_sync(0xffffffffu, cc, off);
    }
    if (lane == 0) { s_rs[wid] = ss; s_rc[wid] = cc; }
    __syncthreads();

    if (tid == 0) {
        float sv = 0.0f;
        int   cv = 0;
        #pragma unroll
        for (int w = 0; w < TPB / 32; w++) { sv += s_rs[w]; cv += s_rc[w]; }
        g_ps[bid] = sv;
        g_pc[bid] = cv;
    }

    // ---- last-block fused finalize (threadfence + ticket) ----------------
    __threadfence();
    if (tid == 0) {
        const unsigned t = atomicAdd(&g_ticket, 1u);
        s_islast = (t == NPART - 1) ? 1 : 0;
    }
    __syncthreads();

    if (s_islast) {
        __threadfence();                   // all partials now visible
        double    sv = 0.0;
        long long cv = 0;
        for (int idx = tid; idx < NPART; idx += TPB) {   // fixed order
            sv += (double)g_ps[idx];
            cv += (long long)g_pc[idx];
        }
        #pragma unroll
        for (int off = 16; off > 0; off >>= 1) {
            sv += __shfl_down_sync(0xffffffffu, sv, off);
            cv += __shfl_down_sync(0xffffffffu, cv, off);
        }
        if (lane == 0) { f_s[wid] = sv; f_c[wid] = cv; }
        __syncthreads();
        if (tid == 0) {
            double    ts = 0.0;
            long long tc = 0;
            #pragma unroll
            for (int w = 0; w < TPB / 32; w++) { ts += f_s[w]; tc += f_c[w]; }
            out[0] = tc ? (float)(ts / (double)tc) : 0.0f;
            g_ticket = 0;                  // reset for next graph replay
        }
    }
}

extern "C" void kernel_launch(void* const* d_in, const int* in_sizes, int n_in,
                              void* d_out, int out_size)
{
    // d_in[0] = z (unused)
    const float* risk  = (const float*)d_in[1];
    const float* time_ = (const float*)d_in[2];
    const int*   event = (const int*)d_in[3];

    dim3 grid(ISPLIT, JSPLIT);
    fused_pair_kernel<<<grid, TPB>>>(risk, time_, event, (float*)d_out);
}

// round 6
// speedup vs baseline: 1.5028x; 1.0114x over previous
#include <cuda_runtime.h>
#include <cuda_bf16.h>

// SurvivalGeometryRegularizer:
//   mask[i][j] = (time[i] < time[j]) && (event[i] == 1)
//   hinge      = relu(1 + risk[i] - risk[j])
//   out        = sum(mask*hinge) / sum(mask)   (0 if count==0)
// z (d_in[0]) is UNUSED. Inputs: [1]=risk f32[B], [2]=time f32[B], [3]=event i32[B].
//
// R6: the R5 inner loop's two-statement if{} compiled to BSSY/BSYNC branch
// regions (ptxas pattern), ~2x instruction bloat. Replace with inline-PTX
// guaranteed predication: setp + @p add + @p add = exactly 5 warp-instr/pair.
// Compacted i-array padded to a multiple of 8 with (+INF,0) sentinels so the
// k-loop is branch-free fully-unrolled x8.
//   - 592 blocks (one full wave, 4/SM), 74 i-splits x 8 j-splits
//   - per-block smem compaction of event rows (2x work cut)
//   - count accumulated as float (integer-valued < 2^24 -> exact)
//   - last-block ticket finalize, fixed-order sums -> bitwise deterministic.

#define BNUM   8192
#define TPB    256
#define ISPLIT 74
#define JSPLIT 8
#define JPT    4
#define JTILE  (TPB * JPT)        // 1024
#define NPART  (ISPLIT * JSPLIT)  // 592 blocks / partial slots
#define MAXROW 128                // >= 111 rows + 8 pad

__device__ float        g_ps[NPART];
__device__ float        g_pc[NPART];
__device__ unsigned int g_ticket;   // zero-init at load; last block resets to 0

__global__ __launch_bounds__(TPB) void fused_pair_kernel(
    const float* __restrict__ risk,
    const float* __restrict__ time_,
    const int*   __restrict__ event,
    float*       __restrict__ out)
{
    __shared__ float2    s_i[MAXROW];      // compacted (t_i, 1+r_i), INF-padded
    __shared__ int       s_wsum[TPB / 32];
    __shared__ int       s_lne;
    __shared__ float     s_rs[TPB / 32];
    __shared__ float     s_rc[TPB / 32];
    __shared__ int       s_islast;
    __shared__ double    f_s[TPB / 32];
    __shared__ double    f_c[TPB / 32];

    const int tid  = threadIdx.x;
    const int lane = tid & 31;
    const int wid  = tid >> 5;
    const int bid  = blockIdx.y * ISPLIT + blockIdx.x;

    // ---- this block's i-range (balanced split of 8192 over 74) ----------
    const int ilo  = (blockIdx.x * BNUM) / ISPLIT;
    const int ihi  = ((blockIdx.x + 1) * BNUM) / ISPLIT;
    const int rows = ihi - ilo;             // 110 or 111

    const int   inr = tid < rows;
    const int   i   = ilo + tid;
    const int   ev  = inr ? event[i] : 0;
    const float tiv = inr ? time_[i] : 0.0f;
    const float aiv = inr ? (1.0f + risk[i]) : 0.0f;

    // ---- this thread's 4 j-columns (coalesced) ---------------------------
    const int j0 = blockIdx.y * JTILE;
    float tj[JPT], nrj[JPT];
    #pragma unroll
    for (int m = 0; m < JPT; m++) {
        const int j = j0 + m * TPB + tid;
        tj[m]  = time_[j];
        nrj[m] = -risk[j];
    }

    // ---- intra-block compaction of event rows into smem ------------------
    int incl = ev;
    #pragma unroll
    for (int off = 1; off < 32; off <<= 1) {
        int y = __shfl_up_sync(0xffffffffu, incl, off);
        if (lane >= off) incl += y;
    }
    if (lane == 31) s_wsum[wid] = incl;
    __syncthreads();

    if (wid == 0) {
        int v = (lane < TPB / 32) ? s_wsum[lane] : 0;
        #pragma unroll
        for (int off = 1; off < TPB / 32; off <<= 1) {
            int y = __shfl_up_sync(0xffffffffu, v, off);
            if (lane >= off) v += y;
        }
        if (lane < TPB / 32) s_wsum[lane] = v;
        if (lane == TPB / 32 - 1) s_lne = v;
    }
    __syncthreads();

    {
        const int base = (wid ? s_wsum[wid - 1] : 0) + (incl - ev);
        if (ev) s_i[base] = make_float2(tiv, aiv);
    }
    __syncthreads();

    const int lne     = s_lne;                     // ~55 event rows
    const int lne_pad = (lne + 7) & ~7;            // multiple of 8, <= 118

    // sentinel pad: t=+INF => setp.lt false => zero contribution
    if (tid < lne_pad - lne)
        s_i[lne + tid] = make_float2(__int_as_float(0x7f800000), 0.0f);
    __syncthreads();

    // ---- main pairwise loop: 5 warp-instr / pair, branch-free ------------
    float s[JPT], c[JPT];
    #pragma unroll
    for (int m = 0; m < JPT; m++) { s[m] = 0.0f; c[m] = 0.0f; }

    for (int k = 0; k < lne_pad; k += 8) {
        #pragma unroll
        for (int u = 0; u < 8; u++) {
            const float2 v = s_i[k + u];          // broadcast LDS.64
            #pragma unroll
            for (int m = 0; m < JPT; m++) {
                const float h = fmaxf(v.y + nrj[m], 0.0f);  // FADD + FMNMX
                asm volatile(
                    "{\n\t"
                    ".reg .pred p;\n\t"
                    "setp.lt.f32 p, %2, %3;\n\t"      // t_i < t_j
                    "@p add.f32 %0, %0, %4;\n\t"      // s += h
                    "@p add.f32 %1, %1, 0f3F800000;\n\t" // c += 1.0
                    "}"
                    : "+f"(s[m]), "+f"(c[m])
                    : "f"(v.x), "f"(tj[m]), "f"(h));
            }
        }
    }

    float ss = (s[0] + s[1]) + (s[2] + s[3]);
    float cc = (c[0] + c[1]) + (c[2] + c[3]);

    // ---- deterministic intra-block reduction -----------------------------
    #pragma unroll
    for (int off = 16; off > 0; off >>= 1) {
        ss += __shfl_down_sync(0xffffffffu, ss, off);
        cc += __shfl_down_sync(0xffffffffu, cc, off);
    }
    if (lane == 0) { s_rs[wid] = ss; s_rc[wid] = cc; }
    __syncthreads();

    if (tid == 0) {
        float sv = 0.0f, cv = 0.0f;
        #pragma unroll
        for (int w = 0; w < TPB / 32; w++) { sv += s_rs[w]; cv += s_rc[w]; }
        g_ps[bid] = sv;
        g_pc[bid] = cv;
    }

    // ---- last-block fused finalize (threadfence + ticket) ----------------
    __threadfence();
    if (tid == 0) {
        const unsigned t = atomicAdd(&g_ticket, 1u);
        s_islast = (t == NPART - 1) ? 1 : 0;
    }
    __syncthreads();

    if (s_islast) {
        __threadfence();                   // all partials now visible
        double sv = 0.0, cv = 0.0;
        for (int idx = tid; idx < NPART; idx += TPB) {   // fixed order
            sv += (double)g_ps[idx];
            cv += (double)g_pc[idx];
        }
        #pragma unroll
        for (int off = 16; off > 0; off >>= 1) {
            sv += __shfl_down_sync(0xffffffffu, sv, off);
            cv += __shfl_down_sync(0xffffffffu, cv, off);
        }
        if (lane == 0) { f_s[wid] = sv; f_c[wid] = cv; }
        __syncthreads();
        if (tid == 0) {
            double ts = 0.0, tc = 0.0;
            #pragma unroll
            for (int w = 0; w < TPB / 32; w++) { ts += f_s[w]; tc += f_c[w]; }
            out[0] = (tc != 0.0) ? (float)(ts / tc) : 0.0f;
            g_ticket = 0;                  // reset for next graph replay
        }
    }
}

extern "C" void kernel_launch(void* const* d_in, const int* in_sizes, int n_in,
                              void* d_out, int out_size)
{
    // d_in[0] = z (unused)
    const float* risk  = (const float*)d_in[1];
    const float* time_ = (const float*)d_in[2];
    const int*   event = (const int*)d_in[3];

    dim3 grid(ISPLIT, JSPLIT);
    fused_pair_kernel<<<grid, TPB>>>(risk, time_, event, (float*)d_out);
}